// round 13
// baseline (speedup 1.0000x reference)
#include <cuda_runtime.h>
#include <cstdint>

// ---------------------------------------------------------------------------
// CompositionalLoss via tree prefix sums, vectorized with f32x2 packed math.
//   a[j] = a[par(j)] + b[j]   (a[root]=0)
//   e[j] = a[j] - t[j],  f[j] = e[j] - b[j]
//   delta(u,v) = e[u] - f[v] - b[lca];  lca==v -> e[u]-e[v]; lca==u -> f[u]-f[v]
//   Only branching nodes are Hip(3) and Chest(1) -> cross LCA is 1 or 3.
// Each thread handles ONE channel of TWO samples (s, s+32) packed in f32x2:
//   - all adds/subs are FFMA2/FADD2-class packed ops (half the fma-pipe work)
//   - |x| via and.b64 (2x LOP3, alu pipe) -> dual-pipe interleave
// Block: 96 threads = 3 warps (channel per warp) x 32 sample-pairs = 64 samples.
// ---------------------------------------------------------------------------

#define NJ 21
#define NPAIRS 210
#define SPB 64
#define THREADS 96
#define MAXBLOCKS 4096
#define TILE_FLOATS (SPB * 63)          // 4032 per array
#define TG_BYTE_OFF (TILE_FLOATS * 4)   // 16128: sTg offset inside sAll
#define S2_BYTE_OFF (32 * 63 * 4)       // 8064: second sample (s+32) offset

typedef unsigned long long u64t;

__device__ float g_partials[MAXBLOCKS];
__device__ unsigned int g_count = 0;    // self-resets each launch (graph-safe)

// Kinematic tree (JOINTS alphabetical): parent index per joint.
__host__ __device__ constexpr int par(int j) {
    switch (j) {
        case 0:  return 3;   case 1:  return 0;   case 2:  return 12;
        case 3:  return 3;   case 4:  return 11;  case 5:  return 7;
        case 6:  return 4;   case 7:  return 9;   case 8:  return 1;
        case 9:  return 3;   case 10: return 5;   case 11: return 8;
        case 12: return 1;   case 13: return 20;  case 14: return 16;
        case 15: return 13;  case 16: return 18;  case 17: return 1;
        case 18: return 3;   case 19: return 14;  default: return 17;
    }
}
__host__ __device__ constexpr int depthf(int j) {
    int d = 0;
    while (par(j) != j) { j = par(j); ++d; }
    return d;
}
__host__ __device__ constexpr int lcaf(int u, int v) {
    int du = depthf(u), dv = depthf(v);
    while (du > dv) { u = par(u); --du; }
    while (dv > du) { v = par(v); --dv; }
    while (u != v) { u = par(u); v = par(v); }
    return u;
}
// Pair enumeration sorted by v (CSE of per-v group terms, short live ranges).
__host__ __device__ constexpr int qv(int q) {
    int v = 1;
    while (v * (v + 1) / 2 <= q) ++v;
    return v;
}
__host__ __device__ constexpr int qu(int q) {
    int v = qv(q);
    return q - v * (v - 1) / 2;
}

// ---- packed f32x2 primitives ----
__device__ __forceinline__ u64t add2(u64t a, u64t b) {
    u64t r;
    asm("add.rn.f32x2 %0, %1, %2;" : "=l"(r) : "l"(a), "l"(b));
    return r;
}
// a - b  (exact: fma(b, -1, a)); avoids depending on sub.f32x2 availability
__device__ __forceinline__ u64t sub2(u64t a, u64t b, u64t neg1) {
    u64t r;
    asm("fma.rn.f32x2 %0, %1, %2, %3;" : "=l"(r) : "l"(b), "l"(neg1), "l"(a));
    return r;
}
__device__ __forceinline__ u64t abs2(u64t a) {
    u64t r;
    asm("and.b64 %0, %1, 0x7FFFFFFF7FFFFFFF;" : "=l"(r) : "l"(a));  // 2x LOP3
    return r;
}
// Load samples (s, s+32) of one feature into a packed f32x2.
__device__ __forceinline__ u64t lds_pair(uint32_t addr) {
    u64t r;
    asm volatile("{\n\t.reg .f32 lo, hi;\n\t"
                 "ld.shared.f32 lo, [%1];\n\t"
                 "ld.shared.f32 hi, [%1+8064];\n\t"   // +32*63 floats
                 "mov.b64 %0, {lo, hi};\n\t}"
                 : "=l"(r) : "r"(addr));
    return r;
}

// Fully-unrolled pair accumulation with compile-time indices.
template <int P, int N>
struct PairRun {
    static __device__ __forceinline__ void run(const u64t (&e)[NJ], const u64t (&f)[NJ],
                                               u64t b1, u64t b3, u64t neg1, u64t (&acc)[2]) {
        PairRun<P, N / 2>::run(e, f, b1, b3, neg1, acc);
        PairRun<P + N / 2, N - N / 2>::run(e, f, b1, b3, neg1, acc);
    }
};
template <int P>
struct PairRun<P, 1> {
    static __device__ __forceinline__ void run(const u64t (&e)[NJ], const u64t (&f)[NJ],
                                               u64t b1, u64t b3, u64t neg1, u64t (&acc)[2]) {
        constexpr int u = qu(P);
        constexpr int v = qv(P);
        constexpr int w = lcaf(u, v);
        static_assert(w == u || w == v || w == 1 || w == 3, "unexpected LCA");
        u64t d;
        if constexpr (w == v)       d = sub2(e[u], e[v], neg1);
        else if constexpr (w == u)  d = sub2(f[u], f[v], neg1);
        else if constexpr (w == 1)  d = sub2(e[u], add2(f[v], b1), neg1);  // CSE per v
        else                        d = sub2(e[u], add2(f[v], b3), neg1);  // CSE per v
        acc[P & 1] = add2(acc[P & 1], abs2(d));
    }
};

__device__ __forceinline__ uint32_t smem_u32(const void* p) {
    return (uint32_t)__cvta_generic_to_shared(p);
}
__device__ __forceinline__ void cp_async16(uint32_t dst, const void* src) {
    asm volatile("cp.async.cg.shared.global [%0], [%1], 16;" :: "r"(dst), "l"(src));
}

__global__ __launch_bounds__(THREADS, 6)
void comploss_kernel(const float* __restrict__ gin, const float* __restrict__ gtg,
                     float* __restrict__ out, int B, float invB, int nblocks) {
    __shared__ __align__(16) float sAll[2 * TILE_FLOATS];   // [sIn | sTg]
    __shared__ float sRed[THREADS / 32];
    __shared__ bool sLast;

    const int tid = threadIdx.x;
    const long long s0 = (long long)blockIdx.x * SPB;
    int nsamp = B - (int)s0;
    if (nsamp > SPB) nsamp = SPB;

    // ---- stage gmem -> smem ----
    if (nsamp == SPB) {
        const float4* gi = reinterpret_cast<const float4*>(gin + s0 * 63);
        const float4* gt = reinterpret_cast<const float4*>(gtg + s0 * 63);
        const uint32_t si = smem_u32(sAll);
        for (int i = tid; i < TILE_FLOATS / 4; i += THREADS) {
            cp_async16(si + i * 16, gi + i);
            cp_async16(si + TG_BYTE_OFF + i * 16, gt + i);
        }
        asm volatile("cp.async.commit_group;");
        asm volatile("cp.async.wait_group 0;" ::: "memory");
    } else {
        // tail: zero-pad missing samples (zeros contribute exactly 0 to L1)
        for (int i = tid; i < TILE_FLOATS; i += THREADS) {
            bool ok = i < nsamp * 63;
            sAll[i]               = ok ? gin[s0 * 63 + i] : 0.0f;
            sAll[TILE_FLOATS + i] = ok ? gtg[s0 * 63 + i] : 0.0f;
        }
    }
    __syncthreads();

    // ---- per-(sample-pair, channel) packed compute ----
    const int c  = tid >> 5;       // channel 0..2, uniform per warp
    const int sp = tid & 31;       // sample pair (sp, sp+32); stride-63: no conflicts
    const uint32_t base = smem_u32(sAll) + (uint32_t)(sp * 63 + c) * 4u;

    const u64t neg1 = 0xBF800000BF800000ULL;   // packed (-1.0f, -1.0f)
    u64t e[NJ], f[NJ], a[NJ];
    u64t b1, b3;

#define LB(j) lds_pair(base + 12u * (j))
#define LT(j) lds_pair(base + TG_BYTE_OFF + 12u * (j))
#define LOADJ(j, apar)                                   \
    { u64t bb = LB(j); u64t tt = LT(j);                  \
      a[j] = add2(apar, bb);                             \
      e[j] = sub2(a[j], tt, neg1);                       \
      f[j] = sub2(e[j], bb, neg1); }

    { u64t bb = LB(3); u64t tt = LT(3);                  // root Hip=3, a=0
      a[3] = 0ULL;
      e[3] = sub2(0ULL, tt, neg1);
      f[3] = sub2(e[3], bb, neg1);
      b3 = bb; }
    LOADJ(0,  a[3]);
    { u64t bb = LB(1); u64t tt = LT(1);                  // Chest=1, keep b1
      a[1] = add2(a[0], bb);
      e[1] = sub2(a[1], tt, neg1);
      f[1] = sub2(e[1], bb, neg1);
      b1 = bb; }
    LOADJ(8,  a[1]);
    LOADJ(12, a[1]);
    LOADJ(17, a[1]);
    LOADJ(2,  a[12]);
    LOADJ(9,  a[3]);
    LOADJ(18, a[3]);
    LOADJ(11, a[8]);
    LOADJ(20, a[17]);
    LOADJ(7,  a[9]);
    LOADJ(16, a[18]);
    LOADJ(4,  a[11]);
    LOADJ(13, a[20]);
    LOADJ(5,  a[7]);
    LOADJ(14, a[16]);
    LOADJ(6,  a[4]);
    LOADJ(15, a[13]);
    LOADJ(10, a[5]);
    LOADJ(19, a[14]);
#undef LOADJ
#undef LB
#undef LT

    u64t acc[2] = {0ULL, 0ULL};
    PairRun<0, NPAIRS>::run(e, f, b1, b3, neg1, acc);

    // unpack & horizontal sum (both samples, this channel)
    float thread_sum;
    {
        unsigned int l0 = (unsigned int)(acc[0] & 0xffffffffu);
        unsigned int h0 = (unsigned int)(acc[0] >> 32);
        unsigned int l1 = (unsigned int)(acc[1] & 0xffffffffu);
        unsigned int h1 = (unsigned int)(acc[1] >> 32);
        thread_sum = (__uint_as_float(l0) + __uint_as_float(h0)) +
                     (__uint_as_float(l1) + __uint_as_float(h1));
    }

    // ---- block reduction ----
#pragma unroll
    for (int o = 16; o > 0; o >>= 1)
        thread_sum += __shfl_down_sync(0xffffffffu, thread_sum, o);
    if ((tid & 31) == 0) sRed[tid >> 5] = thread_sum;
    __syncthreads();
    if (tid == 0) {
        float bs = sRed[0] + sRed[1] + sRed[2];
        g_partials[blockIdx.x] = bs;
        __threadfence();
        unsigned int old = atomicAdd(&g_count, 1u);
        sLast = (old == (unsigned int)(nblocks - 1));
    }
    __syncthreads();

    // ---- last block finishes the global reduction ----
    if (sLast) {
        __threadfence();
        float v = 0.0f;
        for (int i = tid; i < nblocks; i += THREADS) v += g_partials[i];
#pragma unroll
        for (int o = 16; o > 0; o >>= 1)
            v += __shfl_down_sync(0xffffffffu, v, o);
        if ((tid & 31) == 0) sRed[tid >> 5] = v;
        __syncthreads();
        if (tid == 0) {
            out[0] = (sRed[0] + sRed[1] + sRed[2]) * invB;
            g_count = 0;   // deterministic across graph replays
        }
    }
}

extern "C" void kernel_launch(void* const* d_in, const int* in_sizes, int n_in,
                              void* d_out, int out_size) {
    const float* gin = (const float*)d_in[0];   // input  [B, 63]
    const float* gtg = (const float*)d_in[1];   // target [B, 63]
    float* out = (float*)d_out;                 // [1] float32

    const int B = in_sizes[0] / (NJ * 3);
    int nblocks = (B + SPB - 1) / SPB;
    if (nblocks > MAXBLOCKS) nblocks = MAXBLOCKS;  // B=65536 -> 1024, safe

    comploss_kernel<<<nblocks, THREADS>>>(gin, gtg, out, B, 1.0f / (float)B, nblocks);
}

// round 14
// speedup vs baseline: 1.0194x; 1.0194x over previous
#include <cuda_runtime.h>
#include <cstdint>

// ---------------------------------------------------------------------------
// CompositionalLoss via tree prefix sums, vectorized with f32x2 packed math.
//   a[j] = a[par(j)] + b[j]   (a[root]=0)
//   e[j] = a[j] - t[j],  f[j] = e[j] - b[j]
//   delta(u,v) = e[u] - f[v] - b[lca];  lca==v -> e[u]-e[v]; lca==u -> f[u]-f[v]
//   Only branching nodes are Hip(3) and Chest(1) -> cross LCA is 1 or 3.
// Each thread handles ONE channel of TWO samples (s, s+32) packed in f32x2:
//   packed adds/subs on fma pipe, |x| via and.b64 (LOP3, alu pipe).
// Block: 96 threads = 3 warps (channel per warp) x 32 sample-pairs = 64 samples.
// 7 resident blocks/SM (smem-bound) + 4 accumulator chains for ILP.
// ---------------------------------------------------------------------------

#define NJ 21
#define NPAIRS 210
#define SPB 64
#define THREADS 96
#define MAXBLOCKS 4096
#define TILE_FLOATS (SPB * 63)          // 4032 per array
#define TG_BYTE_OFF (TILE_FLOATS * 4)   // 16128: sTg offset inside sAll

typedef unsigned long long u64t;

__device__ float g_partials[MAXBLOCKS];
__device__ unsigned int g_count = 0;    // self-resets each launch (graph-safe)

// Kinematic tree (JOINTS alphabetical): parent index per joint.
__host__ __device__ constexpr int par(int j) {
    switch (j) {
        case 0:  return 3;   case 1:  return 0;   case 2:  return 12;
        case 3:  return 3;   case 4:  return 11;  case 5:  return 7;
        case 6:  return 4;   case 7:  return 9;   case 8:  return 1;
        case 9:  return 3;   case 10: return 5;   case 11: return 8;
        case 12: return 1;   case 13: return 20;  case 14: return 16;
        case 15: return 13;  case 16: return 18;  case 17: return 1;
        case 18: return 3;   case 19: return 14;  default: return 17;
    }
}
__host__ __device__ constexpr int depthf(int j) {
    int d = 0;
    while (par(j) != j) { j = par(j); ++d; }
    return d;
}
__host__ __device__ constexpr int lcaf(int u, int v) {
    int du = depthf(u), dv = depthf(v);
    while (du > dv) { u = par(u); --du; }
    while (dv > du) { v = par(v); --dv; }
    while (u != v) { u = par(u); v = par(v); }
    return u;
}
// Pair enumeration sorted by v (CSE of per-v group terms, short live ranges).
__host__ __device__ constexpr int qv(int q) {
    int v = 1;
    while (v * (v + 1) / 2 <= q) ++v;
    return v;
}
__host__ __device__ constexpr int qu(int q) {
    int v = qv(q);
    return q - v * (v - 1) / 2;
}

// ---- packed f32x2 primitives ----
__device__ __forceinline__ u64t add2(u64t a, u64t b) {
    u64t r;
    asm("add.rn.f32x2 %0, %1, %2;" : "=l"(r) : "l"(a), "l"(b));
    return r;
}
// a - b  (exact: fma(b, -1, a))
__device__ __forceinline__ u64t sub2(u64t a, u64t b, u64t neg1) {
    u64t r;
    asm("fma.rn.f32x2 %0, %1, %2, %3;" : "=l"(r) : "l"(b), "l"(neg1), "l"(a));
    return r;
}
__device__ __forceinline__ u64t abs2(u64t a) {
    u64t r;
    asm("and.b64 %0, %1, 0x7FFFFFFF7FFFFFFF;" : "=l"(r) : "l"(a));  // LOP3 (alu)
    return r;
}
// Load samples (s, s+32) of one feature into a packed f32x2.
__device__ __forceinline__ u64t lds_pair(uint32_t addr) {
    u64t r;
    asm volatile("{\n\t.reg .f32 lo, hi;\n\t"
                 "ld.shared.f32 lo, [%1];\n\t"
                 "ld.shared.f32 hi, [%1+8064];\n\t"   // +32*63 floats
                 "mov.b64 %0, {lo, hi};\n\t}"
                 : "=l"(r) : "r"(addr));
    return r;
}

// Fully-unrolled pair accumulation with compile-time indices; 4 acc chains.
template <int P, int N>
struct PairRun {
    static __device__ __forceinline__ void run(const u64t (&e)[NJ], const u64t (&f)[NJ],
                                               u64t b1, u64t b3, u64t neg1, u64t (&acc)[4]) {
        PairRun<P, N / 2>::run(e, f, b1, b3, neg1, acc);
        PairRun<P + N / 2, N - N / 2>::run(e, f, b1, b3, neg1, acc);
    }
};
template <int P>
struct PairRun<P, 1> {
    static __device__ __forceinline__ void run(const u64t (&e)[NJ], const u64t (&f)[NJ],
                                               u64t b1, u64t b3, u64t neg1, u64t (&acc)[4]) {
        constexpr int u = qu(P);
        constexpr int v = qv(P);
        constexpr int w = lcaf(u, v);
        static_assert(w == u || w == v || w == 1 || w == 3, "unexpected LCA");
        u64t d;
        if constexpr (w == v)       d = sub2(e[u], e[v], neg1);
        else if constexpr (w == u)  d = sub2(f[u], f[v], neg1);
        else if constexpr (w == 1)  d = sub2(e[u], add2(f[v], b1), neg1);  // CSE per v
        else                        d = sub2(e[u], add2(f[v], b3), neg1);  // CSE per v
        acc[P & 3] = add2(acc[P & 3], abs2(d));
    }
};

__device__ __forceinline__ uint32_t smem_u32(const void* p) {
    return (uint32_t)__cvta_generic_to_shared(p);
}
__device__ __forceinline__ void cp_async16(uint32_t dst, const void* src) {
    asm volatile("cp.async.cg.shared.global [%0], [%1], 16;" :: "r"(dst), "l"(src));
}

__global__ __launch_bounds__(THREADS, 7)
void comploss_kernel(const float* __restrict__ gin, const float* __restrict__ gtg,
                     float* __restrict__ out, int B, float invB, int nblocks) {
    __shared__ __align__(16) float sAll[2 * TILE_FLOATS];   // [sIn | sTg]
    __shared__ float sRed[THREADS / 32];
    __shared__ bool sLast;

    const int tid = threadIdx.x;
    const long long s0 = (long long)blockIdx.x * SPB;
    int nsamp = B - (int)s0;
    if (nsamp > SPB) nsamp = SPB;

    // ---- stage gmem -> smem ----
    if (nsamp == SPB) {
        const float4* gi = reinterpret_cast<const float4*>(gin + s0 * 63);
        const float4* gt = reinterpret_cast<const float4*>(gtg + s0 * 63);
        const uint32_t si = smem_u32(sAll);
        for (int i = tid; i < TILE_FLOATS / 4; i += THREADS) {
            cp_async16(si + i * 16, gi + i);
            cp_async16(si + TG_BYTE_OFF + i * 16, gt + i);
        }
        asm volatile("cp.async.commit_group;");
        asm volatile("cp.async.wait_group 0;" ::: "memory");
    } else {
        // tail: zero-pad missing samples (zeros contribute exactly 0 to L1)
        for (int i = tid; i < TILE_FLOATS; i += THREADS) {
            bool ok = i < nsamp * 63;
            sAll[i]               = ok ? gin[s0 * 63 + i] : 0.0f;
            sAll[TILE_FLOATS + i] = ok ? gtg[s0 * 63 + i] : 0.0f;
        }
    }
    __syncthreads();

    // ---- per-(sample-pair, channel) packed compute ----
    const int c  = tid >> 5;       // channel 0..2, uniform per warp
    const int sp = tid & 31;       // sample pair (sp, sp+32); stride-63: no conflicts
    const uint32_t base = smem_u32(sAll) + (uint32_t)(sp * 63 + c) * 4u;

    const u64t neg1 = 0xBF800000BF800000ULL;   // packed (-1.0f, -1.0f)
    u64t e[NJ], f[NJ], a[NJ];
    u64t b1, b3;

#define LB(j) lds_pair(base + 12u * (j))
#define LT(j) lds_pair(base + TG_BYTE_OFF + 12u * (j))
#define LOADJ(j, apar)                                   \
    { u64t bb = LB(j); u64t tt = LT(j);                  \
      a[j] = add2(apar, bb);                             \
      e[j] = sub2(a[j], tt, neg1);                       \
      f[j] = sub2(e[j], bb, neg1); }

    { u64t bb = LB(3); u64t tt = LT(3);                  // root Hip=3, a=0
      a[3] = 0ULL;
      e[3] = sub2(0ULL, tt, neg1);
      f[3] = sub2(e[3], bb, neg1);
      b3 = bb; }
    LOADJ(0,  a[3]);
    { u64t bb = LB(1); u64t tt = LT(1);                  // Chest=1, keep b1
      a[1] = add2(a[0], bb);
      e[1] = sub2(a[1], tt, neg1);
      f[1] = sub2(e[1], bb, neg1);
      b1 = bb; }
    LOADJ(8,  a[1]);
    LOADJ(12, a[1]);
    LOADJ(17, a[1]);
    LOADJ(2,  a[12]);
    LOADJ(9,  a[3]);
    LOADJ(18, a[3]);
    LOADJ(11, a[8]);
    LOADJ(20, a[17]);
    LOADJ(7,  a[9]);
    LOADJ(16, a[18]);
    LOADJ(4,  a[11]);
    LOADJ(13, a[20]);
    LOADJ(5,  a[7]);
    LOADJ(14, a[16]);
    LOADJ(6,  a[4]);
    LOADJ(15, a[13]);
    LOADJ(10, a[5]);
    LOADJ(19, a[14]);
#undef LOADJ
#undef LB
#undef LT

    u64t acc[4] = {0ULL, 0ULL, 0ULL, 0ULL};
    PairRun<0, NPAIRS>::run(e, f, b1, b3, neg1, acc);

    // unpack & horizontal sum (both samples, this channel)
    u64t acc01 = add2(acc[0], acc[1]);
    u64t acc23 = add2(acc[2], acc[3]);
    u64t accT  = add2(acc01, acc23);
    float2 av = *reinterpret_cast<float2*>(&accT);
    float thread_sum = av.x + av.y;

    // ---- block reduction ----
#pragma unroll
    for (int o = 16; o > 0; o >>= 1)
        thread_sum += __shfl_down_sync(0xffffffffu, thread_sum, o);
    if ((tid & 31) == 0) sRed[tid >> 5] = thread_sum;
    __syncthreads();
    if (tid == 0) {
        float bs = sRed[0] + sRed[1] + sRed[2];
        g_partials[blockIdx.x] = bs;
        __threadfence();
        unsigned int old = atomicAdd(&g_count, 1u);
        sLast = (old == (unsigned int)(nblocks - 1));
    }
    __syncthreads();

    // ---- last block finishes the global reduction ----
    if (sLast) {
        __threadfence();
        float v = 0.0f;
        for (int i = tid; i < nblocks; i += THREADS) v += g_partials[i];
#pragma unroll
        for (int o = 16; o > 0; o >>= 1)
            v += __shfl_down_sync(0xffffffffu, v, o);
        if ((tid & 31) == 0) sRed[tid >> 5] = v;
        __syncthreads();
        if (tid == 0) {
            out[0] = (sRed[0] + sRed[1] + sRed[2]) * invB;
            g_count = 0;   // deterministic across graph replays
        }
    }
}

extern "C" void kernel_launch(void* const* d_in, const int* in_sizes, int n_in,
                              void* d_out, int out_size) {
    const float* gin = (const float*)d_in[0];   // input  [B, 63]
    const float* gtg = (const float*)d_in[1];   // target [B, 63]
    float* out = (float*)d_out;                 // [1] float32

    const int B = in_sizes[0] / (NJ * 3);
    int nblocks = (B + SPB - 1) / SPB;
    if (nblocks > MAXBLOCKS) nblocks = MAXBLOCKS;  // B=65536 -> 1024, safe

    comploss_kernel<<<nblocks, THREADS>>>(gin, gtg, out, B, 1.0f / (float)B, nblocks);
}

// round 15
// speedup vs baseline: 1.0583x; 1.0381x over previous
#include <cuda_runtime.h>
#include <cstdint>

// ---------------------------------------------------------------------------
// CompositionalLoss via tree prefix sums, vectorized with f32x2 packed math.
//   a[j] = a[par(j)] + b[j]   (a[root]=0)
//   e[j] = a[j] - t[j],  f[j] = e[j] - b[j]
//   delta(u,v) = e[u] - f[v] - b[lca];  lca==v -> e[u]-e[v]; lca==u -> f[u]-f[v]
//   Only branching nodes are Hip(3) and Chest(1) -> cross LCA is 1 or 3.
// Each thread handles ONE channel of TWO samples (s, s+32) packed in f32x2.
// KEY FIX vs R14: shared loads are plain C++ (NOT asm volatile) so ptxas can
// hoist them into MLP batches instead of a 630-cycle serial LDS chain.
// ---------------------------------------------------------------------------

#define NJ 21
#define NPAIRS 210
#define SPB 64
#define THREADS 96
#define MAXBLOCKS 4096
#define TILE_FLOATS (SPB * 63)          // 4032 per array
#define HI_OFF (32 * 63)                // second sample (s+32) float offset

typedef unsigned long long u64t;

__device__ float g_partials[MAXBLOCKS];
__device__ unsigned int g_count = 0;    // self-resets each launch (graph-safe)

// Kinematic tree (JOINTS alphabetical): parent index per joint.
__host__ __device__ constexpr int par(int j) {
    switch (j) {
        case 0:  return 3;   case 1:  return 0;   case 2:  return 12;
        case 3:  return 3;   case 4:  return 11;  case 5:  return 7;
        case 6:  return 4;   case 7:  return 9;   case 8:  return 1;
        case 9:  return 3;   case 10: return 5;   case 11: return 8;
        case 12: return 1;   case 13: return 20;  case 14: return 16;
        case 15: return 13;  case 16: return 18;  case 17: return 1;
        case 18: return 3;   case 19: return 14;  default: return 17;
    }
}
__host__ __device__ constexpr int depthf(int j) {
    int d = 0;
    while (par(j) != j) { j = par(j); ++d; }
    return d;
}
__host__ __device__ constexpr int lcaf(int u, int v) {
    int du = depthf(u), dv = depthf(v);
    while (du > dv) { u = par(u); --du; }
    while (dv > du) { v = par(v); --dv; }
    while (u != v) { u = par(u); v = par(v); }
    return u;
}
// Pair enumeration sorted by v (CSE of per-v group terms, short live ranges).
__host__ __device__ constexpr int qv(int q) {
    int v = 1;
    while (v * (v + 1) / 2 <= q) ++v;
    return v;
}
__host__ __device__ constexpr int qu(int q) {
    int v = qv(q);
    return q - v * (v - 1) / 2;
}

// ---- packed f32x2 primitives (pure, non-volatile: fully schedulable) ----
__device__ __forceinline__ u64t add2(u64t a, u64t b) {
    u64t r;
    asm("add.rn.f32x2 %0, %1, %2;" : "=l"(r) : "l"(a), "l"(b));
    return r;
}
// a - b  (exact: fma(b, -1, a))
__device__ __forceinline__ u64t sub2(u64t a, u64t b, u64t neg1) {
    u64t r;
    asm("fma.rn.f32x2 %0, %1, %2, %3;" : "=l"(r) : "l"(b), "l"(neg1), "l"(a));
    return r;
}
__device__ __forceinline__ u64t abs2(u64t a) {
    u64t r;
    asm("and.b64 %0, %1, 0x7FFFFFFF7FFFFFFF;" : "=l"(r) : "l"(a));  // LOP3 (alu)
    return r;
}
// Plain C++ shared loads: samples (s, s+32) of one feature -> packed f32x2.
// ptxas is free to hoist/batch these (the R14 version was asm volatile and
// serialized into a ~630-cycle LDS chain).
__device__ __forceinline__ u64t ld2(const float* p) {
    union { float2 f; u64t u; } v;
    v.f.x = p[0];
    v.f.y = p[HI_OFF];
    return v.u;
}

// Fully-unrolled pair accumulation with compile-time indices; 4 acc chains.
template <int P, int N>
struct PairRun {
    static __device__ __forceinline__ void run(const u64t (&e)[NJ], const u64t (&f)[NJ],
                                               u64t b1, u64t b3, u64t neg1, u64t (&acc)[4]) {
        PairRun<P, N / 2>::run(e, f, b1, b3, neg1, acc);
        PairRun<P + N / 2, N - N / 2>::run(e, f, b1, b3, neg1, acc);
    }
};
template <int P>
struct PairRun<P, 1> {
    static __device__ __forceinline__ void run(const u64t (&e)[NJ], const u64t (&f)[NJ],
                                               u64t b1, u64t b3, u64t neg1, u64t (&acc)[4]) {
        constexpr int u = qu(P);
        constexpr int v = qv(P);
        constexpr int w = lcaf(u, v);
        static_assert(w == u || w == v || w == 1 || w == 3, "unexpected LCA");
        u64t d;
        if constexpr (w == v)       d = sub2(e[u], e[v], neg1);
        else if constexpr (w == u)  d = sub2(f[u], f[v], neg1);
        else if constexpr (w == 1)  d = sub2(e[u], add2(f[v], b1), neg1);  // CSE per v
        else                        d = sub2(e[u], add2(f[v], b3), neg1);  // CSE per v
        acc[P & 3] = add2(acc[P & 3], abs2(d));
    }
};

__device__ __forceinline__ uint32_t smem_u32(const void* p) {
    return (uint32_t)__cvta_generic_to_shared(p);
}
__device__ __forceinline__ void cp_async16(uint32_t dst, const void* src) {
    asm volatile("cp.async.cg.shared.global [%0], [%1], 16;" :: "r"(dst), "l"(src));
}

__global__ __launch_bounds__(THREADS, 6)
void comploss_kernel(const float* __restrict__ gin, const float* __restrict__ gtg,
                     float* __restrict__ out, int B, float invB, int nblocks) {
    __shared__ __align__(16) float sIn[TILE_FLOATS];
    __shared__ __align__(16) float sTg[TILE_FLOATS];
    __shared__ float sRed[THREADS / 32];
    __shared__ bool sLast;

    const int tid = threadIdx.x;
    const long long s0 = (long long)blockIdx.x * SPB;
    int nsamp = B - (int)s0;
    if (nsamp > SPB) nsamp = SPB;

    // ---- stage gmem -> smem ----
    if (nsamp == SPB) {
        const float4* gi = reinterpret_cast<const float4*>(gin + s0 * 63);
        const float4* gt = reinterpret_cast<const float4*>(gtg + s0 * 63);
        const uint32_t si = smem_u32(sIn);
        const uint32_t st = smem_u32(sTg);
        for (int i = tid; i < TILE_FLOATS / 4; i += THREADS) {
            cp_async16(si + i * 16, gi + i);
            cp_async16(st + i * 16, gt + i);
        }
        asm volatile("cp.async.commit_group;");
        asm volatile("cp.async.wait_group 0;" ::: "memory");
    } else {
        // tail: zero-pad missing samples (zeros contribute exactly 0 to L1)
        for (int i = tid; i < TILE_FLOATS; i += THREADS) {
            bool ok = i < nsamp * 63;
            sIn[i] = ok ? gin[s0 * 63 + i] : 0.0f;
            sTg[i] = ok ? gtg[s0 * 63 + i] : 0.0f;
        }
    }
    __syncthreads();

    // ---- per-(sample-pair, channel) packed compute ----
    const int c  = tid >> 5;       // channel 0..2, uniform per warp
    const int sp = tid & 31;       // sample pair (sp, sp+32); stride-63: no conflicts
    const float* bp = sIn + sp * 63 + c;
    const float* tp = sTg + sp * 63 + c;

    const u64t neg1 = 0xBF800000BF800000ULL;   // packed (-1.0f, -1.0f)
    u64t e[NJ], f[NJ], a[NJ];
    u64t b1, b3;

#define LOADJ(j, apar)                                   \
    { u64t bb = ld2(bp + 3 * (j)); u64t tt = ld2(tp + 3 * (j)); \
      a[j] = add2(apar, bb);                             \
      e[j] = sub2(a[j], tt, neg1);                       \
      f[j] = sub2(e[j], bb, neg1); }

    { u64t bb = ld2(bp + 9); u64t tt = ld2(tp + 9);      // root Hip=3, a=0
      a[3] = 0ULL;
      e[3] = sub2(0ULL, tt, neg1);
      f[3] = sub2(e[3], bb, neg1);
      b3 = bb; }
    LOADJ(0,  a[3]);
    { u64t bb = ld2(bp + 3); u64t tt = ld2(tp + 3);      // Chest=1, keep b1
      a[1] = add2(a[0], bb);
      e[1] = sub2(a[1], tt, neg1);
      f[1] = sub2(e[1], bb, neg1);
      b1 = bb; }
    LOADJ(8,  a[1]);
    LOADJ(12, a[1]);
    LOADJ(17, a[1]);
    LOADJ(2,  a[12]);
    LOADJ(9,  a[3]);
    LOADJ(18, a[3]);
    LOADJ(11, a[8]);
    LOADJ(20, a[17]);
    LOADJ(7,  a[9]);
    LOADJ(16, a[18]);
    LOADJ(4,  a[11]);
    LOADJ(13, a[20]);
    LOADJ(5,  a[7]);
    LOADJ(14, a[16]);
    LOADJ(6,  a[4]);
    LOADJ(15, a[13]);
    LOADJ(10, a[5]);
    LOADJ(19, a[14]);
#undef LOADJ

    u64t acc[4] = {0ULL, 0ULL, 0ULL, 0ULL};
    PairRun<0, NPAIRS>::run(e, f, b1, b3, neg1, acc);

    // unpack & horizontal sum (both samples, this channel)
    u64t acc01 = add2(acc[0], acc[1]);
    u64t acc23 = add2(acc[2], acc[3]);
    u64t accT  = add2(acc01, acc23);
    union { u64t u; float2 f2; } av; av.u = accT;
    float thread_sum = av.f2.x + av.f2.y;

    // ---- block reduction ----
#pragma unroll
    for (int o = 16; o > 0; o >>= 1)
        thread_sum += __shfl_down_sync(0xffffffffu, thread_sum, o);
    if ((tid & 31) == 0) sRed[tid >> 5] = thread_sum;
    __syncthreads();
    if (tid == 0) {
        float bs = sRed[0] + sRed[1] + sRed[2];
        g_partials[blockIdx.x] = bs;
        __threadfence();
        unsigned int old = atomicAdd(&g_count, 1u);
        sLast = (old == (unsigned int)(nblocks - 1));
    }
    __syncthreads();

    // ---- last block finishes the global reduction ----
    if (sLast) {
        __threadfence();
        float v = 0.0f;
        for (int i = tid; i < nblocks; i += THREADS) v += g_partials[i];
#pragma unroll
        for (int o = 16; o > 0; o >>= 1)
            v += __shfl_down_sync(0xffffffffu, v, o);
        if ((tid & 31) == 0) sRed[tid >> 5] = v;
        __syncthreads();
        if (tid == 0) {
            out[0] = (sRed[0] + sRed[1] + sRed[2]) * invB;
            g_count = 0;   // deterministic across graph replays
        }
    }
}

extern "C" void kernel_launch(void* const* d_in, const int* in_sizes, int n_in,
                              void* d_out, int out_size) {
    const float* gin = (const float*)d_in[0];   // input  [B, 63]
    const float* gtg = (const float*)d_in[1];   // target [B, 63]
    float* out = (float*)d_out;                 // [1] float32

    const int B = in_sizes[0] / (NJ * 3);
    int nblocks = (B + SPB - 1) / SPB;
    if (nblocks > MAXBLOCKS) nblocks = MAXBLOCKS;  // B=65536 -> 1024, safe

    comploss_kernel<<<nblocks, THREADS>>>(gin, gtg, out, B, 1.0f / (float)B, nblocks);
}